// round 10
// baseline (speedup 1.0000x reference)
#include <cuda_runtime.h>
#include <cstdint>

// Closed-form normalization constants.
#define Y00f  0.28209479177387814f    // 1/(2*sqrt(pi))
#define N10f  0.48860251190291992f    // sqrt(3/(4pi))
#define N20f  0.63078313050504001f    // sqrt(5/(4pi))
#define C21f  (-1.09254843059207907f) // -(1/2)*sqrt(15/pi)
#define C22f  0.54627421529603953f    // (1/4)*sqrt(15/pi)
#define K20f  0.35355339059327379f    // 1/(2*sqrt(2))
#define K21f  0.20412414523193152f    // 1/(2*sqrt(6))
#define K30f  0.06415002990995843f    // 1/(9*sqrt(3))
#define K31f  0.04536092116208279f    // sqrt(1/486)
#define K32f  0.02028602047074832f    // sqrt(8/19440)

typedef unsigned long long u64;

__device__ u64   g_A[15];   // packed combined coefficients (lo == hi)
__device__ float g_b5;      // scalar L30 coefficient

__device__ __forceinline__ u64 pk(float lo, float hi) {
    u64 r; asm("mov.b64 %0,{%1,%2};" : "=l"(r) : "f"(lo), "f"(hi)); return r;
}
__device__ __forceinline__ void upk(u64 v, float& lo, float& hi) {
    asm("mov.b64 {%0,%1},%2;" : "=f"(lo), "=f"(hi) : "l"(v));
}
__device__ __forceinline__ u64 f2mul(u64 a, u64 b) {
    u64 d; asm("mul.rn.f32x2 %0,%1,%2;" : "=l"(d) : "l"(a), "l"(b)); return d;
}
__device__ __forceinline__ u64 f2fma(u64 a, u64 b, u64 c) {
    u64 d; asm("fma.rn.f32x2 %0,%1,%2,%3;" : "=l"(d) : "l"(a), "l"(b), "l"(c)); return d;
}
__device__ __forceinline__ u64 f2add(u64 a, u64 b) {
    u64 d; asm("add.rn.f32x2 %0,%1,%2;" : "=l"(d) : "l"(a), "l"(b)); return d;
}

// One-warp setup: fold all norms/scalings into 15 packed coefficients.
__global__ void setup_coeffs_kernel(const float* __restrict__ coeffs) {
    if (threadIdx.x == 0) {
        float c[14];
#pragma unroll
        for (int k = 0; k < 14; k++) c[k] = coeffs[k];
        float b0  =  2.0f * Y00f * c[0];
        float b1  =  Y00f * K20f * c[1];
        float a2  =  N10f * K21f * c[3];
        float a3  = -N10f * K21f * c[4];
        float a4  = -N10f * K21f * c[2];
        float a6  =  N10f * K31f * c[7];
        float a7  = -N10f * K31f * c[8];
        float a8  = -N10f * K31f * c[6];
        float n2  =  N20f * K32f * c[11];
        float q12 =  (4.0f / 9.0f) * C21f * K32f * c[12];
        float q10 =  (4.0f / 9.0f) * C21f * K32f * c[10];
        float e13 =  (4.0f / 9.0f) * C22f * K32f * c[13];
        float e9  =  (8.0f / 9.0f) * C22f * K32f * c[9];
        float w9a = (2.0f / 3.0f) * n2 - e13;
        float cw  = -(2.0f / 9.0f) * n2 + e13;
        float v[15] = { b0, -b1, 2.0f * b1, a2, a3, a4, a6, a7, a8,
                        w9a, cw, q12, q10, -2.0f * e13, e9 };
#pragma unroll
        for (int k = 0; k < 15; k++) g_A[k] = pk(v[k], v[k]);
        g_b5 = Y00f * K30f * c[5];
    }
}

// Per-point prep: MUFU + imm-FFMA only.
struct P8 { float r, t, ct, st, cp, sp, l30b, g3c; };

__device__ __forceinline__ P8 prep(float r, float th, float ph, float b5s) {
    P8 p;
    p.r = r;
    __sincosf(th, &p.st, &p.ct);
    __sincosf(ph, &p.sp, &p.cp);
    p.t = __expf(r * (-1.0f / 6.0f));
    float u = fmaf(r, 4.0f / 9.0f, -4.0f);
    p.l30b = fmaf(u, r, 6.0f) * b5s;
    p.g3c  = fmaf(r, -4.0f / 9.0f, 8.0f / 3.0f);
    return p;
}

__device__ __forceinline__ u64 eval_pair(const P8& p0, const P8& p1,
                                         const u64* __restrict__ A) {
    u64 R   = pk(p0.r,    p1.r),    T   = pk(p0.t,   p1.t);
    u64 CT  = pk(p0.ct,   p1.ct),   ST  = pk(p0.st,  p1.st);
    u64 CP  = pk(p0.cp,   p1.cp),   SP  = pk(p0.sp,  p1.sp);
    u64 L30B = pk(p0.l30b, p1.l30b), G3C = pk(p0.g3c, p1.g3c);

    u64 T2 = f2mul(T, T), T3 = f2mul(T2, T), T6 = f2mul(T3, T3);
    u64 R2 = f2mul(R, R);
    u64 SPSP = f2mul(SP, SP), SPCP = f2mul(SP, CP);
    u64 CTCT = f2mul(CT, CT), ST2 = f2mul(ST, ST), CTST = f2mul(CT, ST);

    u64 X1 = f2fma(CT, __ldg(&A[3]),
                   f2mul(ST, f2fma(CP, __ldg(&A[4]), f2mul(SP, __ldg(&A[5])))));
    u64 B3 = f2fma(R, f2add(X1, __ldg(&A[1])), __ldg(&A[2]));

    u64 X2 = f2fma(CT, __ldg(&A[6]),
                   f2mul(ST, f2fma(CP, __ldg(&A[7]), f2mul(SP, __ldg(&A[8])))));
    u64 G3 = f2mul(R, G3C);
    u64 P2 = f2fma(G3, X2, L30B);

    u64 Y = f2fma(CP, __ldg(&A[11]), f2mul(SP, __ldg(&A[12])));
    u64 Z = f2fma(SPCP, __ldg(&A[14]), f2mul(SPSP, __ldg(&A[13])));
    u64 W = f2fma(ST2, Z, f2fma(CTST, Y, f2fma(CTCT, __ldg(&A[9]), __ldg(&A[10]))));
    u64 B2 = f2fma(R2, W, P2);

    return f2fma(T6, __ldg(&A[0]), f2fma(T3, B3, f2mul(T2, B2)));
}

// ── Bulk-async pipelined main kernel ─────────────────────────────────────
#define THREADS    128
#define TILE_PTS   512                    // points per tile (= 4 per thread)
#define TILE_BYTES (TILE_PTS * 12)        // 6144 B
#define TILE_G     (TILE_PTS / 4)         // 128 float4-groups per tile

__global__ __launch_bounds__(THREADS)
void orbital_eval_kernel(const float* __restrict__ pos,
                         float* __restrict__ out,
                         int nTiles, int n4, int n) {
    __shared__ __align__(16) char buf[2][TILE_BYTES];
    __shared__ u64 mbar[2];

    int tid = threadIdx.x;
    uint32_t mb0 = (uint32_t)__cvta_generic_to_shared(&mbar[0]);
    uint32_t mb1 = (uint32_t)__cvta_generic_to_shared(&mbar[1]);
    uint32_t bb0 = (uint32_t)__cvta_generic_to_shared(&buf[0][0]);
    uint32_t bb1 = (uint32_t)__cvta_generic_to_shared(&buf[1][0]);

    if (tid == 0) {
        asm volatile("mbarrier.init.shared.b64 [%0], %1;" :: "r"(mb0), "r"(1u) : "memory");
        asm volatile("mbarrier.init.shared.b64 [%0], %1;" :: "r"(mb1), "r"(1u) : "memory");
    }
    __syncthreads();

    const u64* A = g_A;
    float b5s = __ldg(&g_b5);

    int tile = blockIdx.x;

    // Prologue: issue first tile into stage 0.
    if (tile < nTiles && tid == 0) {
        asm volatile("mbarrier.arrive.expect_tx.shared.b64 _, [%0], %1;"
                     :: "r"(mb0), "r"((uint32_t)TILE_BYTES) : "memory");
        asm volatile("cp.async.bulk.shared::cta.global.mbarrier::complete_tx::bytes "
                     "[%0], [%1], %2, [%3];"
                     :: "r"(bb0), "l"(pos + (size_t)tile * TILE_PTS * 3),
                        "r"((uint32_t)TILE_BYTES), "r"(mb0) : "memory");
    }

    int ph0 = 0, ph1 = 0;
    int it = 0;
    for (; tile < nTiles; tile += gridDim.x, ++it) {
        int s = it & 1;
        uint32_t mbS = s ? mb1 : mb0;
        uint32_t bbS = s ? bb1 : bb0;

        // Issue the next tile into the other stage (its prior consumption
        // finished at last iteration's __syncthreads()).
        int nextTile = tile + gridDim.x;
        if (nextTile < nTiles && tid == 0) {
            uint32_t mbN = s ? mb0 : mb1;
            uint32_t bbN = s ? bb0 : bb1;
            asm volatile("mbarrier.arrive.expect_tx.shared.b64 _, [%0], %1;"
                         :: "r"(mbN), "r"((uint32_t)TILE_BYTES) : "memory");
            asm volatile("cp.async.bulk.shared::cta.global.mbarrier::complete_tx::bytes "
                         "[%0], [%1], %2, [%3];"
                         :: "r"(bbN), "l"(pos + (size_t)nextTile * TILE_PTS * 3),
                            "r"((uint32_t)TILE_BYTES), "r"(mbN) : "memory");
        }

        // Wait for the current stage to be full.
        {
            int phase = s ? ph1 : ph0;
            uint32_t done;
            asm volatile(
                "{\n\t.reg .pred p;\n\t"
                "mbarrier.try_wait.parity.acquire.cta.shared::cta.b64 p, [%1], %2;\n\t"
                "selp.b32 %0, 1, 0, p;\n\t}"
                : "=r"(done) : "r"(mbS), "r"((uint32_t)phase) : "memory");
            if (!done) {
                asm volatile(
                    "{\n\t.reg .pred P1;\n\t"
                    "WL_%=:\n\t"
                    "mbarrier.try_wait.parity.acquire.cta.shared::cta.b64 P1, [%0], %1, 0x989680;\n\t"
                    "@P1 bra.uni WD_%=;\n\t"
                    "bra.uni WL_%=;\n\t"
                    "WD_%=:\n\t}"
                    :: "r"(mbS), "r"((uint32_t)phase) : "memory");
            }
            if (s) ph1 ^= 1; else ph0 ^= 1;
        }

        // Compute 4 points from smem.
        {
            const char* bp = s ? buf[1] : buf[0];
            const float4* p4 = reinterpret_cast<const float4*>(bp + tid * 48);
            float4 v0 = p4[0];
            float4 v1 = p4[1];
            float4 v2 = p4[2];

            P8 q0 = prep(v0.x, v0.y, v0.z, b5s);
            P8 q1 = prep(v0.w, v1.x, v1.y, b5s);
            u64 r01 = eval_pair(q0, q1, A);
            P8 q2 = prep(v1.z, v1.w, v2.x, b5s);
            P8 q3 = prep(v2.y, v2.z, v2.w, b5s);
            u64 r23 = eval_pair(q2, q3, A);

            float4 o;
            upk(r01, o.x, o.y);
            upk(r23, o.z, o.w);
            int gidx = tile * TILE_G + tid;
            __stcs(reinterpret_cast<float4*>(out) + gidx, o);
        }
        __syncthreads();   // all threads done with stage s before it is refilled
    }

    // Remainder float4-groups beyond full tiles: direct-load path.
    int gid = blockIdx.x * blockDim.x + tid;
    int remBase  = nTiles * TILE_G;
    int remCount = n4 - remBase;
    if (gid < remCount) {
        int i = remBase + gid;
        const float4* p4 = reinterpret_cast<const float4*>(pos);
        float4 v0 = p4[3 * i + 0];
        float4 v1 = p4[3 * i + 1];
        float4 v2 = p4[3 * i + 2];
        P8 q0 = prep(v0.x, v0.y, v0.z, b5s);
        P8 q1 = prep(v0.w, v1.x, v1.y, b5s);
        u64 r01 = eval_pair(q0, q1, A);
        P8 q2 = prep(v1.z, v1.w, v2.x, b5s);
        P8 q3 = prep(v2.y, v2.z, v2.w, b5s);
        u64 r23 = eval_pair(q2, q3, A);
        float4 o;
        upk(r01, o.x, o.y);
        upk(r23, o.z, o.w);
        __stcs(reinterpret_cast<float4*>(out) + i, o);
    }

    // Scalar tail (n % 4 != 0).
    int tail = n - n4 * 4;
    if (gid < tail) {
        int idx = n4 * 4 + gid;
        P8 p = prep(pos[3 * idx], pos[3 * idx + 1], pos[3 * idx + 2], b5s);
        u64 rr = eval_pair(p, p, A);
        float lo, hi; upk(rr, lo, hi);
        out[idx] = lo;
    }
}

extern "C" void kernel_launch(void* const* d_in, const int* in_sizes, int n_in,
                              void* d_out, int out_size) {
    const float* pos    = (const float*)d_in[0];   // (2048, 4096, 3) fp32
    const float* coeffs = (const float*)d_in[1];   // (14,) fp32
    float* out          = (float*)d_out;           // (2048, 4096) fp32

    int n  = out_size;
    int n4 = n / 4;
    int nTiles = n4 / TILE_G;

    setup_coeffs_kernel<<<1, 32>>>(coeffs);

    int blocks = 1776;                 // 148 SMs x 12 blocks
    if (nTiles > 0 && nTiles < blocks) blocks = nTiles;
    if (blocks < 1) blocks = 1;

    orbital_eval_kernel<<<blocks, THREADS>>>(pos, out, nTiles, n4, n);
}